// round 1
// baseline (speedup 1.0000x reference)
#include <cuda_runtime.h>
#include <cstdint>
#include <cstddef>

#define BB 128
#define TT 1000
#define II 64
#define HH 512
#define ALPHA 0.2f

#define CLUSTER 8
#define B_TILE 8      // b rows per cluster (group)
#define H_TILE 64     // h columns per CTA
#define KDIM 576      // H + I
#define NWARP 8
#define KSLICE 72     // K per warp
#define KITERS 9      // 72/8

// ping-pong recurrent state  [2][B][H]
__device__ float g_rbuf[2][BB * HH];

__device__ __forceinline__ uint32_t f2tf32(float f) {
    uint32_t r;
    asm("cvt.rna.tf32.f32 %0, %1;" : "=r"(r) : "f"(f));
    return r;
}

__device__ __forceinline__ void mma_tf32(float c[4], const uint32_t a[4], const uint32_t b[2]) {
    asm volatile(
        "mma.sync.aligned.m16n8k8.row.col.f32.tf32.tf32.f32 "
        "{%0,%1,%2,%3}, {%4,%5,%6,%7}, {%8,%9}, {%0,%1,%2,%3};"
        : "+f"(c[0]), "+f"(c[1]), "+f"(c[2]), "+f"(c[3])
        : "r"(a[0]), "r"(a[1]), "r"(a[2]), "r"(a[3]), "r"(b[0]), "r"(b[1]));
}

__global__ void init_kernel() {
    int i = blockIdx.x * blockDim.x + threadIdx.x;
    if (i < BB * HH) g_rbuf[0][i] = 0.0f;
}

// Persistent recurrence kernel.
// grid = 128 CTAs, clusters of 8. Cluster g covers b rows [g*8, g*8+8),
// CTA rank r within cluster covers h columns [r*64, r*64+64).
// Per step, per CTA: drive[h(64), b(8)] = W_cat[h, 0:576] . rcat[b, 0:576]
// computed as M=64, N=8, K=576 tf32 mma with W fragments resident in registers.
__global__ void __launch_bounds__(256, 1) __cluster_dims__(CLUSTER, 1, 1)
rnn_kernel(const float* __restrict__ x, const float* __restrict__ W_in,
           const float* __restrict__ b_in, const float* __restrict__ W_hh,
           const float* __restrict__ b_hh, float* __restrict__ out_r)
{
    const int tid  = threadIdx.x;
    const int warp = tid >> 5;
    const int lane = tid & 31;
    const int rank = blockIdx.x & (CLUSTER - 1);
    const int bg   = blockIdx.x >> 3;          // b-group 0..15
    const int hbase = rank * H_TILE;
    const int b0g   = bg * B_TILE;

    __shared__ float part[NWARP][H_TILE][B_TILE];   // 16 KB K-reduction buffer
    __shared__ float bias_s[H_TILE];

    if (tid < H_TILE) bias_s[tid] = b_hh[hbase + tid] + b_in[hbase + tid];

    // ---- load W fragments (A operand) into registers, tf32, one time ----
    const int kw = warp * KSLICE;
    uint32_t areg[4][KITERS][4];
#pragma unroll
    for (int mt = 0; mt < 4; mt++) {
#pragma unroll
        for (int it = 0; it < KITERS; it++) {
#pragma unroll
            for (int r = 0; r < 4; r++) {
                int row = (lane >> 2) + ((r & 1) ? 8 : 0);
                int col = (lane & 3) + ((r & 2) ? 4 : 0);
                int h = hbase + mt * 16 + row;
                int k = kw + it * 8 + col;
                float w = (k < HH) ? W_hh[h * HH + k] : W_in[h * II + (k - HH)];
                areg[mt][it][r] = f2tf32(w);
            }
        }
    }
    __syncthreads();

    const int bl = lane >> 2;           // B-frag column (local b) 0..7
    const int bglob_frag = b0g + bl;
    const int kr = lane & 3;

    // epilogue mapping: thread -> (h, b0, b0+1)
    const int eh   = tid >> 2;          // 0..63
    const int eb0  = (tid & 3) * 2;     // 0,2,4,6
    const int ehg  = hbase + eh;
    const int egb0 = b0g + eb0;

    for (int t = 0; t < TT; t++) {
        const float* rbuf_rd = g_rbuf[t & 1];
        float* rbuf_wr = g_rbuf[(t + 1) & 1];

        // ---- B fragments: rcat[b, k] = k<512 ? r_old[b,k] : x[b,t,k-512] ----
        uint32_t breg[KITERS][2];
#pragma unroll
        for (int it = 0; it < KITERS; it++) {
#pragma unroll
            for (int j = 0; j < 2; j++) {
                int k = kw + it * 8 + kr + j * 4;
                float v;
                if (k < HH) v = __ldcg(&rbuf_rd[bglob_frag * HH + k]);
                else        v = __ldg(&x[((size_t)bglob_frag * TT + t) * II + (k - HH)]);
                breg[it][j] = f2tf32(v);
            }
        }

        float c[4][4];
#pragma unroll
        for (int mt = 0; mt < 4; mt++)
#pragma unroll
            for (int r = 0; r < 4; r++) c[mt][r] = 0.0f;

#pragma unroll
        for (int it = 0; it < KITERS; it++)
#pragma unroll
            for (int mt = 0; mt < 4; mt++)
                mma_tf32(c[mt], areg[mt][it], breg[it]);

        // ---- stage partials for 8-way K reduction ----
#pragma unroll
        for (int mt = 0; mt < 4; mt++) {
            int row = mt * 16 + (lane >> 2);
            int col = 2 * (lane & 3);
            *(float2*)&part[warp][row][col]     = make_float2(c[mt][0], c[mt][1]);
            *(float2*)&part[warp][row + 8][col] = make_float2(c[mt][2], c[mt][3]);
        }
        __syncthreads();

        // ---- reduce + bias + tanh + leaky update + writeback ----
        float s0 = 0.0f, s1 = 0.0f;
#pragma unroll
        for (int w = 0; w < NWARP; w++) {
            float2 v = *(const float2*)&part[w][eh][eb0];
            s0 += v.x; s1 += v.y;
        }
        float bias = bias_s[eh];
        float d0 = tanhf(s0 + bias);
        float d1 = tanhf(s1 + bias);
        float r0 = __ldcg(&rbuf_rd[(egb0)     * HH + ehg]);
        float r1 = __ldcg(&rbuf_rd[(egb0 + 1) * HH + ehg]);
        float rn0 = (1.0f - ALPHA) * r0 + ALPHA * d0;
        float rn1 = (1.0f - ALPHA) * r1 + ALPHA * d1;
        __stcg(&rbuf_wr[(egb0)     * HH + ehg], rn0);
        __stcg(&rbuf_wr[(egb0 + 1) * HH + ehg], rn1);
        size_t ob = ((size_t)t * BB + egb0) * HH + ehg;
        out_r[ob]      = rn0;
        out_r[ob + HH] = rn1;

        // ---- cluster barrier: release our r_new writes, acquire peers' ----
        asm volatile("barrier.cluster.arrive.aligned;" ::: "memory");
        asm volatile("barrier.cluster.wait.aligned;"   ::: "memory");
    }
}

// decision[t,b] = dot(output[t,b,:], W_out) + b_out   (1 warp per row)
__global__ void __launch_bounds__(256)
decision_kernel(const float* __restrict__ out_r, const float* __restrict__ W_out,
                const float* __restrict__ b_out, float* __restrict__ dec)
{
    int wg = blockIdx.x * 8 + (threadIdx.x >> 5);
    int lane = threadIdx.x & 31;
    if (wg >= TT * BB) return;
    const float* row = out_r + (size_t)wg * HH;
    float s = 0.0f;
#pragma unroll
    for (int c = 0; c < 4; c++) {
        int h = c * 128 + lane * 4;
        float4 v = *(const float4*)&row[h];
        float4 w = *(const float4*)&W_out[h];
        s += v.x * w.x + v.y * w.y + v.z * w.z + v.w * w.w;
    }
#pragma unroll
    for (int o = 16; o; o >>= 1) s += __shfl_down_sync(0xffffffffu, s, o);
    if (lane == 0) dec[wg] = s + b_out[0];
}

extern "C" void kernel_launch(void* const* d_in, const int* in_sizes, int n_in,
                              void* d_out, int out_size) {
    const float* x     = (const float*)d_in[0];
    const float* W_in  = (const float*)d_in[1];
    const float* b_in  = (const float*)d_in[2];
    const float* W_hh  = (const float*)d_in[3];
    const float* b_hh  = (const float*)d_in[4];
    const float* W_out = (const float*)d_in[5];
    const float* b_out = (const float*)d_in[6];

    float* dec   = (float*)d_out;                       // [T*B]
    float* out_r = (float*)d_out + (size_t)TT * BB;     // [T*B*H]

    init_kernel<<<(BB * HH + 255) / 256, 256>>>();
    rnn_kernel<<<128, 256>>>(x, W_in, b_in, W_hh, b_hh, out_r);
    decision_kernel<<<(TT * BB) / 8, 256>>>(out_r, W_out, b_out, dec);
}

// round 3
// speedup vs baseline: 2.2912x; 2.2912x over previous
#include <cuda_runtime.h>
#include <cuda_fp16.h>
#include <cstdint>
#include <cstddef>

#define BB 128
#define TT 1000
#define II 64
#define HH 512
#define KDIM 576
#define ALPHA 0.2f

#define CLUSTER 8
#define B_TILE 8       // b rows per cluster
#define H_TILE 64      // h rows per CTA
#define NTHR 128       // 4 warps; warp = one 16-row M-tile, full K
#define KQ 36          // 576 / 16 k-steps
#define RSTRIDE 584    // halves per b row in smem (576 + 8 pad, conflict-free)

__device__ __forceinline__ uint32_t s2u(const void* p) {
    return (uint32_t)__cvta_generic_to_shared(p);
}

__device__ __forceinline__ uint32_t h2_as_u32(half2 h) {
    uint32_t u;
    static_assert(sizeof(half2) == 4, "");
    __builtin_memcpy(&u, &h, 4);
    return u;
}

__device__ __forceinline__ void dsmem_st64(uint32_t addr, int rank, unsigned long long v) {
    uint32_t r;
    asm volatile("mapa.shared::cluster.u32 %0, %1, %2;" : "=r"(r) : "r"(addr), "r"(rank));
    asm volatile("st.shared::cluster.u64 [%0], %1;" :: "r"(r), "l"(v) : "memory");
}

__device__ __forceinline__ void mma_f16(float c[4], const uint32_t a[4], uint32_t b0, uint32_t b1) {
    asm volatile(
        "mma.sync.aligned.m16n8k16.row.col.f32.f16.f16.f32 "
        "{%0,%1,%2,%3}, {%4,%5,%6,%7}, {%8,%9}, {%0,%1,%2,%3};"
        : "+f"(c[0]), "+f"(c[1]), "+f"(c[2]), "+f"(c[3])
        : "r"(a[0]), "r"(a[1]), "r"(a[2]), "r"(a[3]), "r"(b0), "r"(b1));
}

__device__ __forceinline__ float tanh_fast(float x) {
    float y;
    asm("tanh.approx.f32 %0, %1;" : "=f"(y) : "f"(x));
    return y;
}

// grid = 128 CTAs in 16 clusters of 8. Cluster g: b rows [g*8, g*8+8).
// CTA rank r: h rows [r*64, r*64+64). Per step, per CTA:
// drive[64h, 8b] = W_cat[64h, 576k] . rcat[8b, 576k], fp16 MMA, fp32 accum.
// W resident in registers; rcat (r fp16 ++ x fp16) in smem, double-buffered;
// r_new broadcast to all cluster CTAs via DSMEM stores; sync = barrier.cluster.
__global__ void __launch_bounds__(NTHR, 1) __cluster_dims__(CLUSTER, 1, 1)
rnn_kernel(const float* __restrict__ x, const float* __restrict__ W_in,
           const float* __restrict__ b_in, const float* __restrict__ W_hh,
           const float* __restrict__ b_hh, float* __restrict__ out_r)
{
    const int tid  = threadIdx.x;
    const int wid  = tid >> 5;            // 0..3 : M-tile
    const int lane = tid & 31;
    const int rank = blockIdx.x & (CLUSTER - 1);
    const int bg   = blockIdx.x >> 3;
    const int hbase = rank * H_TILE;
    const int b0g   = bg * B_TILE;

    __shared__ __align__(16) half  rcat[2][B_TILE][RSTRIDE];  // [buf][b][k]
    __shared__ __align__(16) float staging[4][16][10];

    // zero r-region of buf 0 (r(0) = 0)
    for (int i = tid; i < B_TILE * (HH / 2); i += NTHR) {
        int b = i >> 8, k = (i & 255) * 2;
        *(half2*)&rcat[0][b][k] = __floats2half2_rn(0.f, 0.f);
    }

    // ---- W fragments (A operand) into registers, packed fp16, one time ----
    // a[kq][j]: j0:(h, k..k+1) j1:(h+8, ..) j2:(h, k+8..k+9) j3:(h+8, k+8..)
    const int hA = hbase + wid * 16 + (lane >> 2);
    const int kA = 2 * (lane & 3);
    uint32_t a[KQ][4];
#pragma unroll
    for (int kq = 0; kq < KQ; kq++) {
#pragma unroll
        for (int j = 0; j < 4; j++) {
            int h = hA + ((j & 1) ? 8 : 0);
            int k = kq * 16 + kA + ((j & 2) ? 8 : 0);
            float2 w;
            if (k < HH) w = *(const float2*)&W_hh[h * HH + k];
            else        w = *(const float2*)&W_in[h * II + (k - HH)];
            a[kq][j] = h2_as_u32(__floats2half2_rn(w.x, w.y));
        }
    }

    // epilogue-static mapping: thread -> (b = lane&7, h0 = (lane>>3)*4 .. +3)
    const int eb  = lane & 7;
    const int eh0 = (lane >> 3) * 4;
    const int ehg = hbase + wid * 16 + eh0;   // global h of v[0]
    const int ebg = b0g + eb;                 // global b
    float r_old[4] = {0.f, 0.f, 0.f, 0.f};
    float bias_r[4];
#pragma unroll
    for (int i = 0; i < 4; i++) bias_r[i] = b_hh[ehg + i] + b_in[ehg + i];

    // x staging mapping: thread -> (xb = tid>>4, xi0 = (tid&15)*4)
    const int xb  = tid >> 4;
    const int xi0 = (tid & 15) * 4;
    const float* xrow = &x[(size_t)(b0g + xb) * TT * II + xi0];

    // stage x(0) into buf 0
    {
        float4 xv = *(const float4*)&xrow[0];
        *(half2*)&rcat[0][xb][HH + xi0]     = __floats2half2_rn(xv.x, xv.y);
        *(half2*)&rcat[0][xb][HH + xi0 + 2] = __floats2half2_rn(xv.z, xv.w);
    }
    __syncthreads();

    // B-frag smem addresses (n = lane>>2, k = kq*16 + 2*(lane&3) [+8])
    const int bfr_n = lane >> 2;
    const int bfr_k = 2 * (lane & 3);
    const uint32_t myslot = s2u(&rcat[0][eb][0]) + (uint32_t)(wid * 16 + eh0 + hbase) * 2;
    const uint32_t bufstep = (uint32_t)(B_TILE * RSTRIDE * 2);  // bytes between buf0/buf1

#pragma unroll 1
    for (int t = 0; t < TT; t++) {
        // prefetch x(t+1)
        int tn = (t + 1 < TT) ? t + 1 : TT - 1;
        float4 xv = *(const float4*)&xrow[(size_t)tn * II];

        const half* rb = &rcat[t & 1][bfr_n][bfr_k];

        // ---- MMA: 4 independent accumulator chains over K ----
        float c[4][4];
#pragma unroll
        for (int q = 0; q < 4; q++)
#pragma unroll
            for (int r = 0; r < 4; r++) c[q][r] = 0.f;

#pragma unroll
        for (int i = 0; i < 9; i++) {
#pragma unroll
            for (int q = 0; q < 4; q++) {
                const int kq = q * 9 + i;
                uint32_t bq0 = *(const uint32_t*)&rb[kq * 16];
                uint32_t bq1 = *(const uint32_t*)&rb[kq * 16 + 8];
                mma_f16(c[q], a[kq], bq0, bq1);
            }
        }
        float cf[4];
#pragma unroll
        for (int r = 0; r < 4; r++)
            cf[r] = (c[0][r] + c[1][r]) + (c[2][r] + c[3][r]);

        // ---- transpose via per-warp staging: (h, 2b) -> (b, 4h) ----
        {
            int hl = lane >> 2, bc = 2 * (lane & 3);
            *(float2*)&staging[wid][hl][bc]     = make_float2(cf[0], cf[1]);
            *(float2*)&staging[wid][hl + 8][bc] = make_float2(cf[2], cf[3]);
        }
        __syncwarp();

        float rn[4];
#pragma unroll
        for (int i = 0; i < 4; i++) {
            float s = staging[wid][eh0 + i][eb] + bias_r[i];
            float d = tanh_fast(s);
            rn[i] = (1.0f - ALPHA) * r_old[i] + ALPHA * d;
            r_old[i] = rn[i];
        }

        // out_r[t][b][h0..h0+3]
        *(float4*)&out_r[((size_t)t * BB + ebg) * HH + ehg] =
            make_float4(rn[0], rn[1], rn[2], rn[3]);

        // stage x(t+1) into next buffer (local, disjoint from peer r-writes)
        {
            half* xd = &rcat[(t + 1) & 1][xb][HH + xi0];
            *(half2*)&xd[0] = __floats2half2_rn(xv.x, xv.y);
            *(half2*)&xd[2] = __floats2half2_rn(xv.z, xv.w);
        }

        // broadcast r_new (fp16) into every cluster CTA's next buffer
        {
            half2 p0 = __floats2half2_rn(rn[0], rn[1]);
            half2 p1 = __floats2half2_rn(rn[2], rn[3]);
            unsigned long long pv =
                (unsigned long long)h2_as_u32(p0)
                | ((unsigned long long)h2_as_u32(p1) << 32);
            uint32_t loc = myslot + ((t + 1) & 1) * bufstep;
#pragma unroll
            for (int cta = 0; cta < CLUSTER; cta++)
                dsmem_st64(loc, cta, pv);
        }

        // cluster barrier: orders DSMEM stores + local STS for everyone
        asm volatile("barrier.cluster.arrive.aligned;" ::: "memory");
        asm volatile("barrier.cluster.wait.aligned;"   ::: "memory");
    }
}

// decision[t,b] = dot(output[t,b,:], W_out) + b_out   (1 warp per row)
__global__ void __launch_bounds__(256)
decision_kernel(const float* __restrict__ out_r, const float* __restrict__ W_out,
                const float* __restrict__ b_out, float* __restrict__ dec)
{
    int wg = blockIdx.x * 8 + (threadIdx.x >> 5);
    int lane = threadIdx.x & 31;
    if (wg >= TT * BB) return;
    const float* row = out_r + (size_t)wg * HH;
    float s = 0.0f;
#pragma unroll
    for (int c = 0; c < 4; c++) {
        int h = c * 128 + lane * 4;
        float4 v = *(const float4*)&row[h];
        float4 w = *(const float4*)&W_out[h];
        s += v.x * w.x + v.y * w.y + v.z * w.z + v.w * w.w;
    }
#pragma unroll
    for (int o = 16; o; o >>= 1) s += __shfl_down_sync(0xffffffffu, s, o);
    if (lane == 0) dec[wg] = s + b_out[0];
}

extern "C" void kernel_launch(void* const* d_in, const int* in_sizes, int n_in,
                              void* d_out, int out_size) {
    const float* x     = (const float*)d_in[0];
    const float* W_in  = (const float*)d_in[1];
    const float* b_in  = (const float*)d_in[2];
    const float* W_hh  = (const float*)d_in[3];
    const float* b_hh  = (const float*)d_in[4];
    const float* W_out = (const float*)d_in[5];
    const float* b_out = (const float*)d_in[6];

    float* dec   = (float*)d_out;                    // [T*B]
    float* out_r = (float*)d_out + (size_t)TT * BB;  // [T*B*H]

    rnn_kernel<<<BB, NTHR>>>(x, W_in, b_in, W_hh, b_hh, out_r);
    decision_kernel<<<(TT * BB) / 8, 256>>>(out_r, W_out, b_out, dec);
}

// round 4
// speedup vs baseline: 3.4142x; 1.4902x over previous
#include <cuda_runtime.h>
#include <cuda_fp16.h>
#include <cstdint>
#include <cstddef>

#define BB 128
#define TT 1000
#define II 64
#define HH 512
#define ALPHA 0.2f

#define CLUSTER 4
#define B_TILE 8        // b rows per cluster
#define H_TILE 128      // h rows per CTA
#define NTHR 256        // 8 warps, warp = one 16-row M-tile, full K
#define NWARP 8
#define KQ 36           // 576/16 k-steps (32 r + 4 x)
#define RCNT 2304       // u32 per buffer: 36*8*4*2

// rcat u32 layout: idx(kq, n, m, j) = ((kq*8 + n)*4 + m)*2 + j
// u32(kq,n,m,0) = halves (k=16kq+2m, +1) ; j=1 -> (k=16kq+8+2m, +1), column b=n.
// Reader (MMA B frag): lane-linear, one conflict-free LDS.64 per kq.
__device__ __forceinline__ int ridx(int kq, int n, int m, int j) {
    return ((kq * 8 + n) * 4 + m) * 2 + j;
}

__device__ __forceinline__ uint32_t s2u(const void* p) {
    return (uint32_t)__cvta_generic_to_shared(p);
}

__device__ __forceinline__ uint32_t h2_as_u32(half2 h) {
    uint32_t u;
    __builtin_memcpy(&u, &h, 4);
    return u;
}

__device__ __forceinline__ void dsmem_st64(uint32_t addr, uint32_t rank, unsigned long long v) {
    uint32_t r;
    asm volatile("mapa.shared::cluster.u32 %0, %1, %2;" : "=r"(r) : "r"(addr), "r"(rank));
    asm volatile("st.shared::cluster.u64 [%0], %1;" :: "r"(r), "l"(v) : "memory");
}

__device__ __forceinline__ void mbar_arrive_remote(uint32_t addr, uint32_t rank) {
    uint32_t r;
    asm volatile("mapa.shared::cluster.u32 %0, %1, %2;" : "=r"(r) : "r"(addr), "r"(rank));
    asm volatile("mbarrier.arrive.release.cluster.shared::cluster.b64 _, [%0];" :: "r"(r) : "memory");
}

__device__ __forceinline__ void mbar_wait_acq(uint32_t addr, uint32_t parity) {
    asm volatile(
        "{\n\t"
        ".reg .pred P;\n"
        "WL%=:\n\t"
        "mbarrier.try_wait.parity.acquire.cluster.shared::cta.b64 P, [%0], %1;\n\t"
        "@!P bra WL%=;\n\t"
        "}"
        :: "r"(addr), "r"(parity) : "memory");
}

__device__ __forceinline__ void mma_f16(float c[4], const uint32_t a[4], uint32_t b0, uint32_t b1) {
    asm volatile(
        "mma.sync.aligned.m16n8k16.row.col.f32.f16.f16.f32 "
        "{%0,%1,%2,%3}, {%4,%5,%6,%7}, {%8,%9}, {%0,%1,%2,%3};"
        : "+f"(c[0]), "+f"(c[1]), "+f"(c[2]), "+f"(c[3])
        : "r"(a[0]), "r"(a[1]), "r"(a[2]), "r"(a[3]), "r"(b0), "r"(b1));
}

__device__ __forceinline__ float tanh_fast(float x) {
    float y;
    asm("tanh.approx.f32 %0, %1;" : "=f"(y) : "f"(x));
    return y;
}

// grid = 64 CTAs in 16 clusters of 4. Cluster g: b rows [g*8, g*8+8).
// CTA rank r: h rows [r*128, r*128+128). Per step per CTA:
// drive[128h, 8b] = W_cat[128h, 576k] . rcat[8b, 576k] (fp16 MMA, fp32 acc),
// W register-resident; state exchanged via DSMEM st64 into peers' next buffer;
// sync via distributed mbarriers (remote arrive.release + try_wait.acquire).
__global__ void __launch_bounds__(NTHR, 1) __cluster_dims__(CLUSTER, 1, 1)
rnn_kernel(const float* __restrict__ x, const float* __restrict__ W_in,
           const float* __restrict__ b_in, const float* __restrict__ W_hh,
           const float* __restrict__ b_hh, float* __restrict__ out_r)
{
    const int tid  = threadIdx.x;
    const int wid  = tid >> 5;
    const int lane = tid & 31;
    const int rank = blockIdx.x & (CLUSTER - 1);
    const int bg   = blockIdx.x >> 2;
    const int hbase = rank * H_TILE;
    const int b0g   = bg * B_TILE;

    __shared__ __align__(16) uint32_t rbuf[2][RCNT];
    __shared__ __align__(16) float staging[NWARP][16][12];
    __shared__ __align__(8) unsigned long long mbar;

    if (tid == 0)
        asm volatile("mbarrier.init.shared.b64 [%0], %1;"
                     :: "r"(s2u(&mbar)), "r"(CLUSTER) : "memory");

    // zero buf0 (r(0) = 0; x region overwritten below)
    for (int i = tid; i < RCNT; i += NTHR) rbuf[0][i] = 0u;

    // ---- W fragments (A operand) into registers, packed fp16, once ----
    const int hA = hbase + wid * 16 + (lane >> 2);
    const int kA = 2 * (lane & 3);
    uint32_t a[KQ][4];
#pragma unroll
    for (int kq = 0; kq < KQ; kq++) {
#pragma unroll
        for (int j = 0; j < 4; j++) {
            int h = hA + ((j & 1) ? 8 : 0);
            int k = kq * 16 + kA + ((j & 2) ? 8 : 0);
            float2 w;
            if (k < HH) w = *(const float2*)&W_hh[h * HH + k];
            else        w = *(const float2*)&W_in[h * II + (k - HH)];
            a[kq][j] = h2_as_u32(__floats2half2_rn(w.x, w.y));
        }
    }

    // ---- epilogue / writer mapping: thread -> (b = wn, warp kq block, m = wm)
    const int wn = lane >> 2;            // local b 0..7
    const int wm = lane & 3;             // fragment m 0..3
    const int ebg = b0g + wn;            // global b
    const int kq_g = rank * 8 + wid;     // global kq of owned r slice
    // owned h (CTA-local): wid*16 + {2wm, 2wm+1, 8+2wm, 9+2wm}
    const int hl0 = wid * 16 + 2 * wm;
    float bias_r[4];
#pragma unroll
    for (int i = 0; i < 4; i++) {
        int hl = hl0 + ((i >> 1) ? 8 : 0) + (i & 1);
        bias_r[i] = b_hh[hbase + hl] + b_in[hbase + hl];
    }
    float r_old[4] = {0.f, 0.f, 0.f, 0.f};
    const int sidx = ridx(kq_g, wn, wm, 0);

    // ---- x staging mapping: one u32 per thread ----
    const int xj  = tid & 1;
    const int xm  = (tid >> 1) & 3;
    const int xkq = 32 + ((tid >> 3) & 3);
    const int xn  = tid >> 5;
    const int xi0 = (xkq - 32) * 16 + xj * 8 + 2 * xm;
    const float* xrow = &x[(size_t)(b0g + xn) * TT * II + xi0];
    const int xidx = ridx(xkq, xn, xm, xj);

    // stage x(0)
    {
        float2 xv = *(const float2*)&xrow[0];
        rbuf[0][xidx] = h2_as_u32(__floats2half2_rn(xv.x, xv.y));
    }
    __syncthreads();
    // cluster-wide: mbarrier init + buf0 visible before any remote traffic
    asm volatile("barrier.cluster.arrive.aligned;" ::: "memory");
    asm volatile("barrier.cluster.wait.aligned;"   ::: "memory");

    const uint32_t mbar_a = s2u(&mbar);

#pragma unroll 1
    for (int t = 0; t < TT; t++) {
        const int p = t & 1;
        // prefetch x(t+1)
        int tn = (t + 1 < TT) ? t + 1 : TT - 1;
        float2 xv = *(const float2*)&xrow[(size_t)tn * II];

        const uint32_t* rb = &rbuf[p][lane * 2];

        // ---- MMA: 4 independent chains over K, B frags = lane-linear LDS.64 ----
        float c[4][4];
#pragma unroll
        for (int q = 0; q < 4; q++)
#pragma unroll
            for (int r = 0; r < 4; r++) c[q][r] = 0.f;

#pragma unroll
        for (int i = 0; i < 9; i++) {
#pragma unroll
            for (int q = 0; q < 4; q++) {
                const int kq = q * 9 + i;
                uint2 bv = *(const uint2*)&rb[kq * 64];
                mma_f16(c[q], a[kq], bv.x, bv.y);
            }
        }
        float cf[4];
#pragma unroll
        for (int r = 0; r < 4; r++)
            cf[r] = (c[0][r] + c[1][r]) + (c[2][r] + c[3][r]);

        // ---- transpose via per-warp staging: (row, 2col) -> (4rows, col) ----
        {
            int rr = lane >> 2, cc = 2 * (lane & 3);
            *(float2*)&staging[wid][rr][cc]     = make_float2(cf[0], cf[1]);
            *(float2*)&staging[wid][rr + 8][cc] = make_float2(cf[2], cf[3]);
        }
        __syncwarp();

        float rn[4];
#pragma unroll
        for (int i = 0; i < 4; i++) {
            int row = 2 * wm + ((i >> 1) ? 8 : 0) + (i & 1);
            float s = staging[wid][row][wn] + bias_r[i];
            float d = tanh_fast(s);
            rn[i] = (1.0f - ALPHA) * r_old[i] + ALPHA * d;
            r_old[i] = rn[i];
        }

        // ---- pack owned fragment pair and broadcast into next buffer ----
        unsigned long long pv =
            (unsigned long long)h2_as_u32(__floats2half2_rn(rn[0], rn[1]))
            | ((unsigned long long)h2_as_u32(__floats2half2_rn(rn[2], rn[3])) << 32);
        uint32_t* dstb = rbuf[p ^ 1];
        *(unsigned long long*)&dstb[sidx] = pv;            // self, plain STS
        uint32_t daddr = s2u(&dstb[sidx]);
#pragma unroll
        for (int cc = 1; cc < CLUSTER; cc++) {
            uint32_t rdst = (rank + cc) & (CLUSTER - 1);
            dsmem_st64(daddr, rdst, pv);
        }
        // stage x(t+1) (local; disjoint from peers' r writes)
        dstb[xidx] = h2_as_u32(__floats2half2_rn(xv.x, xv.y));

        __syncthreads();
        if (tid < CLUSTER) mbar_arrive_remote(mbar_a, (uint32_t)tid);

        // out_r[t][b][h...] — hidden under the mbarrier wait
        {
            size_t ob = ((size_t)t * BB + ebg) * HH + hbase + hl0;
            *(float2*)&out_r[ob]     = make_float2(rn[0], rn[1]);
            *(float2*)&out_r[ob + 8] = make_float2(rn[2], rn[3]);
        }

        mbar_wait_acq(mbar_a, (uint32_t)p);
    }
}

// decision[t,b] = dot(output[t,b,:], W_out) + b_out   (1 warp per row)
__global__ void __launch_bounds__(256)
decision_kernel(const float* __restrict__ out_r, const float* __restrict__ W_out,
                const float* __restrict__ b_out, float* __restrict__ dec)
{
    int wg = blockIdx.x * 8 + (threadIdx.x >> 5);
    int lane = threadIdx.x & 31;
    if (wg >= TT * BB) return;
    const float* row = out_r + (size_t)wg * HH;
    float s = 0.0f;
#pragma unroll
    for (int c = 0; c < 4; c++) {
        int h = c * 128 + lane * 4;
        float4 v = *(const float4*)&row[h];
        float4 w = *(const float4*)&W_out[h];
        s += v.x * w.x + v.y * w.y + v.z * w.z + v.w * w.w;
    }
#pragma unroll
    for (int o = 16; o; o >>= 1) s += __shfl_down_sync(0xffffffffu, s, o);
    if (lane == 0) dec[wg] = s + b_out[0];
}

extern "C" void kernel_launch(void* const* d_in, const int* in_sizes, int n_in,
                              void* d_out, int out_size) {
    const float* x     = (const float*)d_in[0];
    const float* W_in  = (const float*)d_in[1];
    const float* b_in  = (const float*)d_in[2];
    const float* W_hh  = (const float*)d_in[3];
    const float* b_hh  = (const float*)d_in[4];
    const float* W_out = (const float*)d_in[5];
    const float* b_out = (const float*)d_in[6];

    float* dec   = (float*)d_out;                    // [T*B]
    float* out_r = (float*)d_out + (size_t)TT * BB;  // [T*B*H]

    rnn_kernel<<<BB / 2, NTHR>>>(x, W_in, b_in, W_hh, b_hh, out_r);
    decision_kernel<<<(TT * BB) / 8, 256>>>(out_r, W_out, b_out, dec);
}